// round 2
// baseline (speedup 1.0000x reference)
#include <cuda_runtime.h>
#include <math.h>

// ToneStack: 3 cascaded low-shelf biquads over x:[64, 480000] fp32.
// Exact blocked-recurrence decomposition, f32x2-packed filtering passes:
//   pass_zero : per-chunk zero-state filtering (2 chunks/thread, packed) -> f_k
//   scanA/B/C : hierarchical affine scan s_{k+1} = T s_k + f_k (T = A^CHUNK)
//   pass_final: per-chunk filtering from exact entry state (packed), writes y.

#define TLEN   480000
#define NROW   64
#define CHUNK  192
#define NCHUNK 2500      // TLEN / CHUNK
#define NPAIR  1250      // NCHUNK / 2
#define NGSZ   50
#define NGROUP 50        // NCHUNK / NGSZ

typedef unsigned long long u64_t;

__device__ float g_coef[15];                       // per stage: b0, c1, c2, -a1, -a2
__device__ float g_T[36];                          // A^CHUNK
__device__ float g_Tg[36];                         // A^(CHUNK*NGSZ)
__device__ float g_states[NROW * NCHUNK * 6];      // f_k, then overwritten w/ entry states
__device__ float g_grp[NROW * NGROUP * 6];         // group zero-entry finals
__device__ float g_entry[NROW * NGROUP * 6];       // group entry states

// ------------------------------------------------------------ f32x2 utils --

__device__ __forceinline__ u64_t ffma2(u64_t a, u64_t b, u64_t c) {
    u64_t d;
    asm("fma.rn.f32x2 %0, %1, %2, %3;" : "=l"(d) : "l"(a), "l"(b), "l"(c));
    return d;
}
__device__ __forceinline__ u64_t fmul2(u64_t a, u64_t b) {
    u64_t d;
    asm("mul.rn.f32x2 %0, %1, %2;" : "=l"(d) : "l"(a), "l"(b));
    return d;
}
__device__ __forceinline__ u64_t pk2(float lo, float hi) {
    u64_t r;
    asm("mov.b64 %0, {%1, %2};" : "=l"(r) : "f"(lo), "f"(hi));
    return r;
}
__device__ __forceinline__ void upk2(u64_t v, float& lo, float& hi) {
    asm("mov.b64 {%0, %1}, %2;" : "=f"(lo), "=f"(hi) : "l"(v));
}

// ---------------------------------------------------------------- setup ----

__device__ void shelf_coefs(double fc, double gdb, double Q, double* out) {
    const double PI = 3.14159265358979323846;
    double A  = pow(10.0, gdb / 40.0);
    double w0 = 2.0 * PI * fc / 48000.0;
    double al = sin(w0) / (2.0 * Q);
    double cw = cos(w0);
    double sq = sqrt(A);
    double b0 = A * ((A + 1.0) - (A - 1.0) * cw + 2.0 * sq * al);
    double b1 = 2.0 * A * ((A - 1.0) - (A + 1.0) * cw);
    double b2 = A * ((A + 1.0) - (A - 1.0) * cw - 2.0 * sq * al);
    double a0 = (A + 1.0) + (A - 1.0) * cw + 2.0 * sq * al;
    double a1 = -2.0 * ((A - 1.0) + (A + 1.0) * cw);
    double a2 = (A + 1.0) + (A - 1.0) * cw - 2.0 * sq * al;
    b0 /= a0; b1 /= a0; b2 /= a0; a1 /= a0; a2 /= a0;
    out[0] = b0;
    out[1] = b1 - a1 * b0;   // c1
    out[2] = b2 - a2 * b0;   // c2
    out[3] = -a1;
    out[4] = -a2;
}

// D = A*B (6x6), 36 threads; D must not alias A_/B_
#define MATMUL(D, A_, B_)                                                     \
    do {                                                                      \
        if (tid < 36) {                                                       \
            int r_ = tid / 6, c_ = tid % 6;                                   \
            float acc_ = 0.f;                                                 \
            for (int k_ = 0; k_ < 6; k_++)                                    \
                acc_ += (A_)[r_ * 6 + k_] * (B_)[k_ * 6 + c_];                \
            (D)[tid] = acc_;                                                  \
        }                                                                     \
        __syncthreads();                                                      \
    } while (0)

__global__ void setup_kernel(const float* lg, const float* mg, const float* mfc,
                             const float* mq, const float* hg) {
    __shared__ double scoef[15];
    __shared__ float M0[36], M1[36], M2[36], M3[36];
    int tid = threadIdx.x;

    if (tid == 0) {
        double c[5];
        shelf_coefs(120.0, (double)*lg, (double)0.707f, c);
        for (int i = 0; i < 5; i++) { scoef[i] = c[i];      g_coef[i]      = (float)c[i]; }
        shelf_coefs((double)*mfc, (double)*mg, (double)*mq, c);
        for (int i = 0; i < 5; i++) { scoef[5 + i] = c[i];  g_coef[5 + i]  = (float)c[i]; }
        shelf_coefs(4000.0, (double)*hg, (double)0.707f, c);
        for (int i = 0; i < 5; i++) { scoef[10 + i] = c[i]; g_coef[10 + i] = (float)c[i]; }
    }
    __syncthreads();

    // One-step 6x6 homogeneous matrix A: column j = step(e_j, x=0)
    if (tid < 6) {
        double z[6] = {0, 0, 0, 0, 0, 0};
        z[tid] = 1.0;
        double u = 0.0;
        double ns[6];
        for (int st = 0; st < 3; st++) {
            double b0  = scoef[st * 5 + 0], c1 = scoef[st * 5 + 1], c2 = scoef[st * 5 + 2];
            double na1 = scoef[st * 5 + 3], na2 = scoef[st * 5 + 4];
            double z1 = z[2 * st], z2 = z[2 * st + 1];
            double y = b0 * u + z1;
            ns[2 * st]     = c1 * u + na1 * z1 + z2;
            ns[2 * st + 1] = c2 * u + na2 * z1;
            u = y;
        }
        for (int i = 0; i < 6; i++) M0[i * 6 + tid] = (float)ns[i];
    }
    __syncthreads();

    // T = A^192 = A^128 * A^64
    MATMUL(M1, M0, M0);   // A^2
    MATMUL(M2, M1, M1);   // A^4
    MATMUL(M1, M2, M2);   // A^8
    MATMUL(M2, M1, M1);   // A^16
    MATMUL(M1, M2, M2);   // A^32
    MATMUL(M2, M1, M1);   // A^64
    MATMUL(M3, M2, M2);   // A^128
    MATMUL(M0, M3, M2);   // A^192 = T
    if (tid < 36) g_T[tid] = M0[tid];
    __syncthreads();

    // Tg = T^50 = (T^25)^2, T^25 = T^16 * T^8 * T
    MATMUL(M1, M0, M0);   // T^2
    MATMUL(M2, M1, M1);   // T^4
    MATMUL(M3, M2, M2);   // T^8
    MATMUL(M2, M3, M3);   // T^16
    MATMUL(M1, M2, M3);   // T^24
    MATMUL(M2, M1, M0);   // T^25
    MATMUL(M3, M2, M2);   // T^50
    if (tid < 36) g_Tg[tid] = M3[tid];
}

// ------------------------------------------------------- packed filtering --

__device__ __forceinline__ u64_t step2(u64_t u, u64_t z[6], const u64_t k[15]) {
    // stage 1
    u64_t y0 = ffma2(k[0], u, z[0]);
    u64_t t0 = ffma2(k[3], z[0], z[1]);
    z[1] = ffma2(k[2], u, fmul2(k[4], z[0]));
    z[0] = ffma2(k[1], u, t0);
    // stage 2
    u64_t y1 = ffma2(k[5], y0, z[2]);
    u64_t t1 = ffma2(k[8], z[2], z[3]);
    z[3] = ffma2(k[7], y0, fmul2(k[9], z[2]));
    z[2] = ffma2(k[6], y0, t1);
    // stage 3
    u64_t y2 = ffma2(k[10], y1, z[4]);
    u64_t t2 = ffma2(k[13], z[4], z[5]);
    z[5] = ffma2(k[12], y1, fmul2(k[14], z[4]));
    z[4] = ffma2(k[11], y1, t2);
    return y2;
}

__global__ __launch_bounds__(256) void pass_zero(const float* __restrict__ x) {
    int t = blockIdx.x * blockDim.x + threadIdx.x;
    if (t >= NROW * NPAIR) return;
    int r = t / NPAIR, p = t % NPAIR;
    size_t base = (size_t)r * TLEN + (size_t)p * 2 * CHUNK;
    const float4* xp0 = reinterpret_cast<const float4*>(x + base);
    const float4* xp1 = xp0 + CHUNK / 4;
    u64_t k2[15];
#pragma unroll
    for (int i = 0; i < 15; i++) { float c = g_coef[i]; k2[i] = pk2(c, c); }
    u64_t z[6] = {0, 0, 0, 0, 0, 0};
#pragma unroll 4
    for (int i = 0; i < CHUNK / 4; i++) {
        float4 a = xp0[i];
        float4 b = xp1[i];
        step2(pk2(a.x, b.x), z, k2);
        step2(pk2(a.y, b.y), z, k2);
        step2(pk2(a.z, b.z), z, k2);
        step2(pk2(a.w, b.w), z, k2);
    }
    float* f = &g_states[((size_t)r * NCHUNK + (size_t)p * 2) * 6];
#pragma unroll
    for (int i = 0; i < 6; i++) {
        float lo, hi;
        upk2(z[i], lo, hi);
        f[i] = lo;
        f[6 + i] = hi;
    }
}

__global__ __launch_bounds__(256) void pass_final(const float* __restrict__ x,
                                                  float* __restrict__ y) {
    int t = blockIdx.x * blockDim.x + threadIdx.x;
    if (t >= NROW * NPAIR) return;
    int r = t / NPAIR, p = t % NPAIR;
    size_t base = (size_t)r * TLEN + (size_t)p * 2 * CHUNK;
    const float4* xp0 = reinterpret_cast<const float4*>(x + base);
    const float4* xp1 = xp0 + CHUNK / 4;
    float4* yp0 = reinterpret_cast<float4*>(y + base);
    float4* yp1 = yp0 + CHUNK / 4;
    u64_t k2[15];
#pragma unroll
    for (int i = 0; i < 15; i++) { float c = g_coef[i]; k2[i] = pk2(c, c); }
    const float* si = &g_states[((size_t)r * NCHUNK + (size_t)p * 2) * 6];
    u64_t z[6];
#pragma unroll
    for (int i = 0; i < 6; i++) z[i] = pk2(si[i], si[6 + i]);
#pragma unroll 4
    for (int i = 0; i < CHUNK / 4; i++) {
        float4 a = xp0[i];
        float4 b = xp1[i];
        u64_t r0 = step2(pk2(a.x, b.x), z, k2);
        u64_t r1 = step2(pk2(a.y, b.y), z, k2);
        u64_t r2 = step2(pk2(a.z, b.z), z, k2);
        u64_t r3 = step2(pk2(a.w, b.w), z, k2);
        float4 o0, o1;
        upk2(r0, o0.x, o1.x);
        upk2(r1, o0.y, o1.y);
        upk2(r2, o0.z, o1.z);
        upk2(r3, o0.w, o1.w);
        yp0[i] = o0;
        yp1[i] = o1;
    }
}

// ------------------------------------------------------------------ scans --

// scanA: per (row, group) zero-entry scan of NGSZ chunk finals -> group final.
// Batched double-buffer prefetch (5 steps = 30 floats) to hide L2 latency.
__global__ void scanA() {
    int t = blockIdx.x * blockDim.x + threadIdx.x;
    if (t >= NROW * NGROUP) return;
    int r = t / NGROUP, g = t % NGROUP;
    float T[36];
#pragma unroll
    for (int i = 0; i < 36; i++) T[i] = g_T[i];
    const float* f = &g_states[((size_t)r * NCHUNK + (size_t)g * NGSZ) * 6];
    float s[6] = {0, 0, 0, 0, 0, 0};
    float buf0[30], buf1[30];
#pragma unroll
    for (int j = 0; j < 30; j++) buf0[j] = f[j];
#pragma unroll
    for (int b = 0; b < 10; b++) {
        float* cur = (b & 1) ? buf1 : buf0;
        float* nxt = (b & 1) ? buf0 : buf1;
        if (b < 9) {
#pragma unroll
            for (int j = 0; j < 30; j++) nxt[j] = f[(b + 1) * 30 + j];
        }
#pragma unroll
        for (int i = 0; i < 5; i++) {
            float ns[6];
#pragma unroll
            for (int j = 0; j < 6; j++) {
                float acc = cur[i * 6 + j];
#pragma unroll
                for (int kk = 0; kk < 6; kk++) acc = fmaf(T[j * 6 + kk], s[kk], acc);
                ns[j] = acc;
            }
#pragma unroll
            for (int j = 0; j < 6; j++) s[j] = ns[j];
        }
    }
    float* o = &g_grp[(size_t)t * 6];
#pragma unroll
    for (int j = 0; j < 6; j++) o[j] = s[j];
}

// scanB: serial cross-group scan per row. One warp per row; warp bulk-loads the
// row's group finals into SMEM (coalesced, MLP-parallel), lane 0 scans from LDS.
__global__ __launch_bounds__(512) void scanB() {
    __shared__ float sf[16 * NGROUP * 6];
    int wid = threadIdx.x >> 5, lane = threadIdx.x & 31;
    int row = blockIdx.x * 16 + wid;
    const float* gp = &g_grp[(size_t)row * NGROUP * 6];
    for (int i = lane; i < NGROUP * 6; i += 32) sf[wid * NGROUP * 6 + i] = gp[i];
    __syncwarp();
    if (lane == 0) {
        float T[36];
#pragma unroll
        for (int i = 0; i < 36; i++) T[i] = g_Tg[i];
        float s[6] = {0, 0, 0, 0, 0, 0};
        float* eb = &g_entry[(size_t)row * NGROUP * 6];
        const float* fb = &sf[wid * NGROUP * 6];
        for (int g = 0; g < NGROUP; g++) {
#pragma unroll
            for (int j = 0; j < 6; j++) eb[g * 6 + j] = s[j];
            float ns[6];
#pragma unroll
            for (int j = 0; j < 6; j++) {
                float acc = fb[g * 6 + j];
#pragma unroll
                for (int kk = 0; kk < 6; kk++) acc = fmaf(T[j * 6 + kk], s[kk], acc);
                ns[j] = acc;
            }
#pragma unroll
            for (int j = 0; j < 6; j++) s[j] = ns[j];
        }
    }
}

// scanC: per (row, group) scan from the true group-entry state; writes each
// chunk's entry state back over g_states. Same batched prefetch as scanA.
__global__ void scanC() {
    int t = blockIdx.x * blockDim.x + threadIdx.x;
    if (t >= NROW * NGROUP) return;
    int r = t / NGROUP, g = t % NGROUP;
    float T[36];
#pragma unroll
    for (int i = 0; i < 36; i++) T[i] = g_T[i];
    float* f = &g_states[((size_t)r * NCHUNK + (size_t)g * NGSZ) * 6];
    float s[6];
    const float* e = &g_entry[(size_t)t * 6];
#pragma unroll
    for (int j = 0; j < 6; j++) s[j] = e[j];
    float buf0[30], buf1[30];
#pragma unroll
    for (int j = 0; j < 30; j++) buf0[j] = f[j];
#pragma unroll
    for (int b = 0; b < 10; b++) {
        float* cur = (b & 1) ? buf1 : buf0;
        float* nxt = (b & 1) ? buf0 : buf1;
        if (b < 9) {
#pragma unroll
            for (int j = 0; j < 30; j++) nxt[j] = f[(b + 1) * 30 + j];
        }
#pragma unroll
        for (int i = 0; i < 5; i++) {
            int idx = b * 5 + i;
#pragma unroll
            for (int j = 0; j < 6; j++) f[idx * 6 + j] = s[j];  // entry state
            float ns[6];
#pragma unroll
            for (int j = 0; j < 6; j++) {
                float acc = cur[i * 6 + j];
#pragma unroll
                for (int kk = 0; kk < 6; kk++) acc = fmaf(T[j * 6 + kk], s[kk], acc);
                ns[j] = acc;
            }
#pragma unroll
            for (int j = 0; j < 6; j++) s[j] = ns[j];
        }
    }
}

// ----------------------------------------------------------------- launch --

extern "C" void kernel_launch(void* const* d_in, const int* in_sizes, int n_in,
                              void* d_out, int out_size) {
    const float* x   = (const float*)d_in[0];
    const float* lg  = (const float*)d_in[1];
    const float* mg  = (const float*)d_in[2];
    const float* mfc = (const float*)d_in[3];
    const float* mq  = (const float*)d_in[4];
    const float* hg  = (const float*)d_in[5];
    float* y = (float*)d_out;

    setup_kernel<<<1, 64>>>(lg, mg, mfc, mq, hg);

    int nth = NROW * NPAIR;
    int blocks = (nth + 255) / 256;
    pass_zero<<<blocks, 256>>>(x);

    int ng = NROW * NGROUP;
    scanA<<<(ng + 127) / 128, 128>>>();
    scanB<<<4, 512>>>();
    scanC<<<(ng + 127) / 128, 128>>>();

    pass_final<<<blocks, 256>>>(x, y);
}

// round 3
// speedup vs baseline: 2.2196x; 2.2196x over previous
#include <cuda_runtime.h>
#include <math.h>

// ToneStack: 3 cascaded low-shelf biquads over x:[64, 480000] fp32.
// Blocked-recurrence decomposition with coalesced smem-staged passes:
//   pass_zero : per-chunk zero-state filtering -> final states f_k
//   scan_fused: per-row hierarchical affine scan s_{k+1} = T s_k + f_k
//   pass_final: per-chunk filtering from exact entry state, writes y.
// Each warp owns 32 consecutive chunks; gmem IO goes through a padded smem
// transpose so all LDG/STG are coalesced (8 lines/instr instead of 32).

#define TLEN   480000
#define NROW   64
#define CHUNK  256
#define CROW   1875            // chunks per row (TLEN / CHUNK)
#define NCH    (NROW * CROW)   // 120000 chunks total (flat; rows align to chunks)
#define NWARP  (NCH / 32)      // 3750
#define NGROUP 25
#define NGSZ   75              // NGROUP * NGSZ = CROW

__device__ float g_coef[15];          // per stage: b0, c1, c2, -a1, -a2
__device__ float g_T[36];             // A^CHUNK
__device__ float g_Tg[36];            // A^(CHUNK*NGSZ)
__device__ float g_states[NCH * 6];   // f_k, then overwritten with entry states

// ---------------------------------------------------------------- setup ----

__device__ void shelf_coefs(double fc, double gdb, double Q, double* out) {
    const double PI = 3.14159265358979323846;
    double A  = pow(10.0, gdb / 40.0);
    double w0 = 2.0 * PI * fc / 48000.0;
    double al = sin(w0) / (2.0 * Q);
    double cw = cos(w0);
    double sq = sqrt(A);
    double b0 = A * ((A + 1.0) - (A - 1.0) * cw + 2.0 * sq * al);
    double b1 = 2.0 * A * ((A - 1.0) - (A + 1.0) * cw);
    double b2 = A * ((A + 1.0) - (A - 1.0) * cw - 2.0 * sq * al);
    double a0 = (A + 1.0) + (A - 1.0) * cw + 2.0 * sq * al;
    double a1 = -2.0 * ((A - 1.0) + (A + 1.0) * cw);
    double a2 = (A + 1.0) + (A - 1.0) * cw - 2.0 * sq * al;
    b0 /= a0; b1 /= a0; b2 /= a0; a1 /= a0; a2 /= a0;
    out[0] = b0;
    out[1] = b1 - a1 * b0;   // c1
    out[2] = b2 - a2 * b0;   // c2
    out[3] = -a1;
    out[4] = -a2;
}

// D = A*B (6x6), 36 threads; D must not alias A_/B_
#define MATMUL(D, A_, B_)                                                     \
    do {                                                                      \
        if (tid < 36) {                                                       \
            int r_ = tid / 6, c_ = tid % 6;                                   \
            float acc_ = 0.f;                                                 \
            for (int k_ = 0; k_ < 6; k_++)                                    \
                acc_ += (A_)[r_ * 6 + k_] * (B_)[k_ * 6 + c_];                \
            (D)[tid] = acc_;                                                  \
        }                                                                     \
        __syncthreads();                                                      \
    } while (0)

__global__ void setup_kernel(const float* lg, const float* mg, const float* mfc,
                             const float* mq, const float* hg) {
    __shared__ double scoef[15];
    __shared__ float M0[36], M1[36], M2[36], M3[36], M4[36];
    int tid = threadIdx.x;

    if (tid == 0) {
        double c[5];
        shelf_coefs(120.0, (double)*lg, (double)0.707f, c);
        for (int i = 0; i < 5; i++) { scoef[i] = c[i];      g_coef[i]      = (float)c[i]; }
        shelf_coefs((double)*mfc, (double)*mg, (double)*mq, c);
        for (int i = 0; i < 5; i++) { scoef[5 + i] = c[i];  g_coef[5 + i]  = (float)c[i]; }
        shelf_coefs(4000.0, (double)*hg, (double)0.707f, c);
        for (int i = 0; i < 5; i++) { scoef[10 + i] = c[i]; g_coef[10 + i] = (float)c[i]; }
    }
    __syncthreads();

    // One-step 6x6 homogeneous matrix A: column j = step(e_j, x=0)
    if (tid < 6) {
        double z[6] = {0, 0, 0, 0, 0, 0};
        z[tid] = 1.0;
        double u = 0.0;
        double ns[6];
        for (int st = 0; st < 3; st++) {
            double b0  = scoef[st * 5 + 0], c1 = scoef[st * 5 + 1], c2 = scoef[st * 5 + 2];
            double na1 = scoef[st * 5 + 3], na2 = scoef[st * 5 + 4];
            double z1 = z[2 * st], z2 = z[2 * st + 1];
            double y = b0 * u + z1;
            ns[2 * st]     = c1 * u + na1 * z1 + z2;
            ns[2 * st + 1] = c2 * u + na2 * z1;
            u = y;
        }
        for (int i = 0; i < 6; i++) M0[i * 6 + tid] = (float)ns[i];
    }
    __syncthreads();

    // T = A^256 : 8 squarings, ping-pong M0 <-> M1
    for (int s = 0; s < 4; s++) {
        MATMUL(M1, M0, M0);
        MATMUL(M0, M1, M1);
    }
    if (tid < 36) g_T[tid] = M0[tid];
    __syncthreads();

    // Tg = T^75 = T^64 * T^8 * T^2 * T
    MATMUL(M1, M0, M0);   // T^2
    MATMUL(M2, M1, M1);   // T^4
    MATMUL(M3, M2, M2);   // T^8
    MATMUL(M2, M3, M3);   // T^16
    MATMUL(M4, M2, M2);   // T^32
    MATMUL(M2, M4, M4);   // T^64
    MATMUL(M4, M2, M3);   // T^72
    MATMUL(M2, M4, M1);   // T^74
    MATMUL(M4, M2, M0);   // T^75
    if (tid < 36) g_Tg[tid] = M4[tid];
}

// -------------------------------------------------------------- filtering --

__device__ __forceinline__ float step_all(float u, float z[6], const float k[15]) {
    // stage 1
    float y0 = fmaf(k[0], u, z[0]);
    float t0 = fmaf(k[3], z[0], z[1]);
    z[1] = fmaf(k[2], u, k[4] * z[0]);
    z[0] = fmaf(k[1], u, t0);
    // stage 2
    float y1 = fmaf(k[5], y0, z[2]);
    float t1 = fmaf(k[8], z[2], z[3]);
    z[3] = fmaf(k[7], y0, k[9] * z[2]);
    z[2] = fmaf(k[6], y0, t1);
    // stage 3
    float y2 = fmaf(k[10], y1, z[4]);
    float t2 = fmaf(k[13], z[4], z[5]);
    z[5] = fmaf(k[12], y1, k[14] * z[4]);
    z[4] = fmaf(k[11], y1, t2);
    return y2;
}

// Warp-local staged tile: 32 segments (= chunks) x 16 samples, rows padded to
// 20 floats so LDS.128 per-lane row reads are bank-conflict-free.

__global__ __launch_bounds__(128) void pass_zero(const float* __restrict__ x) {
    __shared__ float sbuf[4][32][20];
    int w = blockIdx.x * 4 + (threadIdx.x >> 5);
    if (w >= NWARP) return;
    int lane = threadIdx.x & 31;
    float (*buf)[20] = sbuf[(threadIdx.x >> 5) & 3];
    const float* xw = x + (size_t)w * (32 * CHUNK);

    float k[15];
#pragma unroll
    for (int i = 0; i < 15; i++) k[i] = g_coef[i];
    float z[6] = {0, 0, 0, 0, 0, 0};

    int seg = lane >> 2;            // 0..7 within q-group
    int off = (lane & 3) * 4;       // 0,4,8,12 floats
    float4 pre[4];
#pragma unroll
    for (int q = 0; q < 4; q++)
        pre[q] = *(const float4*)(xw + (q * 8 + seg) * CHUNK + off);

    for (int t = 0; t < 16; t++) {
#pragma unroll
        for (int q = 0; q < 4; q++)
            *(float4*)&buf[q * 8 + seg][off] = pre[q];
        __syncwarp();
        if (t < 15) {
#pragma unroll
            for (int q = 0; q < 4; q++)
                pre[q] = *(const float4*)(xw + (q * 8 + seg) * CHUNK + (t + 1) * 16 + off);
        }
        const float4* my = (const float4*)buf[lane];
#pragma unroll
        for (int j = 0; j < 4; j++) {
            float4 v = my[j];
            step_all(v.x, z, k);
            step_all(v.y, z, k);
            step_all(v.z, z, k);
            step_all(v.w, z, k);
        }
        __syncwarp();
    }
    float* f = &g_states[(size_t)(w * 32 + lane) * 6];
#pragma unroll
    for (int j = 0; j < 6; j++) f[j] = z[j];
}

__global__ __launch_bounds__(128) void pass_final(const float* __restrict__ x,
                                                  float* __restrict__ y) {
    __shared__ float sbuf[4][32][20];
    int w = blockIdx.x * 4 + (threadIdx.x >> 5);
    if (w >= NWARP) return;
    int lane = threadIdx.x & 31;
    float (*buf)[20] = sbuf[(threadIdx.x >> 5) & 3];
    const float* xw = x + (size_t)w * (32 * CHUNK);
    float* yw = y + (size_t)w * (32 * CHUNK);

    float k[15];
#pragma unroll
    for (int i = 0; i < 15; i++) k[i] = g_coef[i];
    float z[6];
    const float* si = &g_states[(size_t)(w * 32 + lane) * 6];
#pragma unroll
    for (int j = 0; j < 6; j++) z[j] = si[j];

    int seg = lane >> 2;
    int off = (lane & 3) * 4;
    float4 pre[4];
#pragma unroll
    for (int q = 0; q < 4; q++)
        pre[q] = *(const float4*)(xw + (q * 8 + seg) * CHUNK + off);

    for (int t = 0; t < 16; t++) {
#pragma unroll
        for (int q = 0; q < 4; q++)
            *(float4*)&buf[q * 8 + seg][off] = pre[q];
        __syncwarp();
        if (t < 15) {
#pragma unroll
            for (int q = 0; q < 4; q++)
                pre[q] = *(const float4*)(xw + (q * 8 + seg) * CHUNK + (t + 1) * 16 + off);
        }
        float4* my = (float4*)buf[lane];
#pragma unroll
        for (int j = 0; j < 4; j++) {
            float4 v = my[j];
            float4 o;
            o.x = step_all(v.x, z, k);
            o.y = step_all(v.y, z, k);
            o.z = step_all(v.z, z, k);
            o.w = step_all(v.w, z, k);
            my[j] = o;
        }
        __syncwarp();
#pragma unroll
        for (int q = 0; q < 4; q++) {
            float4 v = *(const float4*)&buf[q * 8 + seg][off];
            *(float4*)(yw + (q * 8 + seg) * CHUNK + t * 16 + off) = v;
        }
        __syncwarp();
    }
}

// ------------------------------------------------------------ fused scan --

// One block per row. Stage the row's 1875 chunk-finals (45KB) in smem, run
// the 3-phase hierarchical scan entirely from LDS, write entry states back.
__global__ __launch_bounds__(128) void scan_fused() {
    __shared__ float sf[CROW * 6];          // 11250 floats
    __shared__ float sT[36], sTg[36];
    __shared__ float grp[NGROUP][6], ent[NGROUP][6];
    int r = blockIdx.x, tid = threadIdx.x;
    float* gs = &g_states[(size_t)r * CROW * 6];

    for (int i = tid; i < CROW * 6 / 2; i += 128)
        ((float2*)sf)[i] = ((const float2*)gs)[i];
    if (tid < 36) { sT[tid] = g_T[tid]; sTg[tid] = g_Tg[tid]; }
    __syncthreads();

    // phase 1: zero-entry scan within each group
    if (tid < NGROUP) {
        float T[36];
#pragma unroll
        for (int i = 0; i < 36; i++) T[i] = sT[i];
        float s[6] = {0, 0, 0, 0, 0, 0};
        const float* fb = &sf[tid * NGSZ * 6];
        for (int i = 0; i < NGSZ; i++) {
            float ns[6];
#pragma unroll
            for (int j = 0; j < 6; j++) {
                float acc = fb[i * 6 + j];
#pragma unroll
                for (int kk = 0; kk < 6; kk++) acc = fmaf(T[j * 6 + kk], s[kk], acc);
                ns[j] = acc;
            }
#pragma unroll
            for (int j = 0; j < 6; j++) s[j] = ns[j];
        }
#pragma unroll
        for (int j = 0; j < 6; j++) grp[tid][j] = s[j];
    }
    __syncthreads();

    // phase 2: serial cross-group scan
    if (tid == 0) {
        float T[36];
#pragma unroll
        for (int i = 0; i < 36; i++) T[i] = sTg[i];
        float s[6] = {0, 0, 0, 0, 0, 0};
        for (int g = 0; g < NGROUP; g++) {
#pragma unroll
            for (int j = 0; j < 6; j++) ent[g][j] = s[j];
            float ns[6];
#pragma unroll
            for (int j = 0; j < 6; j++) {
                float acc = grp[g][j];
#pragma unroll
                for (int kk = 0; kk < 6; kk++) acc = fmaf(T[j * 6 + kk], s[kk], acc);
                ns[j] = acc;
            }
#pragma unroll
            for (int j = 0; j < 6; j++) s[j] = ns[j];
        }
    }
    __syncthreads();

    // phase 3: scan within group from true entry, overwrite finals w/ entries
    if (tid < NGROUP) {
        float T[36];
#pragma unroll
        for (int i = 0; i < 36; i++) T[i] = sT[i];
        float s[6];
#pragma unroll
        for (int j = 0; j < 6; j++) s[j] = ent[tid][j];
        float* fb = &sf[tid * NGSZ * 6];
        for (int i = 0; i < NGSZ; i++) {
            float fv[6];
#pragma unroll
            for (int j = 0; j < 6; j++) { fv[j] = fb[i * 6 + j]; fb[i * 6 + j] = s[j]; }
            float ns[6];
#pragma unroll
            for (int j = 0; j < 6; j++) {
                float acc = fv[j];
#pragma unroll
                for (int kk = 0; kk < 6; kk++) acc = fmaf(T[j * 6 + kk], s[kk], acc);
                ns[j] = acc;
            }
#pragma unroll
            for (int j = 0; j < 6; j++) s[j] = ns[j];
        }
    }
    __syncthreads();

    for (int i = tid; i < CROW * 6 / 2; i += 128)
        ((float2*)gs)[i] = ((const float2*)sf)[i];
}

// ----------------------------------------------------------------- launch --

extern "C" void kernel_launch(void* const* d_in, const int* in_sizes, int n_in,
                              void* d_out, int out_size) {
    const float* x   = (const float*)d_in[0];
    const float* lg  = (const float*)d_in[1];
    const float* mg  = (const float*)d_in[2];
    const float* mfc = (const float*)d_in[3];
    const float* mq  = (const float*)d_in[4];
    const float* hg  = (const float*)d_in[5];
    float* y = (float*)d_out;

    setup_kernel<<<1, 256>>>(lg, mg, mfc, mq, hg);

    int pblocks = (NWARP + 3) / 4;   // 938 blocks of 4 warps
    pass_zero<<<pblocks, 128>>>(x);
    scan_fused<<<NROW, 128>>>();
    pass_final<<<pblocks, 128>>>(x, y);
}